// round 7
// baseline (speedup 1.0000x reference)
#include <cuda_runtime.h>
#include <cuda_bf16.h>

#define BB 64
#define SS 512
#define II 256
#define HH 512
#define G4 2048
#define NCTA 128   // 512 hidden / 4 per CTA

// ---------------- scratch (device globals: no allocation allowed) ----------------
__device__ float g_xpT[(size_t)SS * G4 * BB];   // x_proj transposed: [t][c][b], 256 MiB
__device__ float g_hbuf[2][HH * BB];            // ping-pong h broadcast: [j][b]
__device__ unsigned g_ctr;

__global__ void init_ctr_k() { g_ctr = 0u; }

// ---------------- GEMM1: xpT[t][c][b] = sum_i x[b][t][i]*W[i][c] + bias[c] ----------------
// grid = (16 c-tiles of 128, 512 t), block = 256. Tile: 128c x 64b, K=256 in BK=32 chunks.
__global__ __launch_bounds__(256) void gemm1_k(const float* __restrict__ x,
                                               const float* __restrict__ W,
                                               const float* __restrict__ bias) {
    __shared__ float Ws[32][132];
    __shared__ float xs[32][68];
    const int t  = blockIdx.y;
    const int c0 = blockIdx.x * 128;
    const int tid = threadIdx.x;
    const int tx = tid & 15;   // b group: 4 batches
    const int ty = tid >> 4;   // c group: 8 cols

    float acc[8][4];
#pragma unroll
    for (int i = 0; i < 8; ++i)
#pragma unroll
        for (int j = 0; j < 4; ++j) acc[i][j] = 0.f;

    for (int kk = 0; kk < II; kk += 32) {
#pragma unroll
        for (int i = 0; i < 16; ++i) {          // Ws: 32x128, coalesced along c
            int idx = i * 256 + tid;
            int k = idx >> 7, cl = idx & 127;
            Ws[k][cl] = W[(size_t)(kk + k) * G4 + c0 + cl];
        }
#pragma unroll
        for (int i = 0; i < 8; ++i) {           // xs: 32k x 64b, coalesced along k
            int idx = i * 256 + tid;
            int bl = idx >> 5, k = idx & 31;
            xs[k][bl] = x[((size_t)bl * SS + t) * II + kk + k];
        }
        __syncthreads();
#pragma unroll
        for (int k = 0; k < 32; ++k) {
            float4 xv = *(const float4*)&xs[k][tx * 4];
            float4 w0 = *(const float4*)&Ws[k][ty * 8];
            float4 w1 = *(const float4*)&Ws[k][ty * 8 + 4];
            float wv[8]  = {w0.x, w0.y, w0.z, w0.w, w1.x, w1.y, w1.z, w1.w};
            float xvv[4] = {xv.x, xv.y, xv.z, xv.w};
#pragma unroll
            for (int i = 0; i < 8; ++i)
#pragma unroll
                for (int j = 0; j < 4; ++j) acc[i][j] += wv[i] * xvv[j];
        }
        __syncthreads();
    }

#pragma unroll
    for (int i = 0; i < 8; ++i) {
        int c = c0 + ty * 8 + i;
        float bb = bias[c];
        float4 o = make_float4(acc[i][0] + bb, acc[i][1] + bb, acc[i][2] + bb, acc[i][3] + bb);
        *(float4*)&g_xpT[((size_t)t * G4 + c) * BB + tx * 4] = o;   // coalesced 256B rows
    }
}

// ---------------- recurrence helpers ----------------
__device__ __forceinline__ float sigf(float v) {
    v = fminf(fmaxf(v, -30.f), 30.f);
    return 1.f / (1.f + __expf(-v));
}
__device__ __forceinline__ float tanhf_fast(float v) {
    v = fminf(fmaxf(v, -15.f), 15.f);
    float e = __expf(-2.f * v);
    return (1.f - e) / (1.f + e);
}

#define STAGE(ch) do {                                                            \
    const float* src_ = rb + (ch) * 64 * BB;                                      \
    float* dst_ = hs + (ch) * 64 * BB;                                            \
    _Pragma("unroll")                                                             \
    for (int v_ = 0; v_ < 4; ++v_) {                                              \
        int idx_ = v_ * 256 + tid;                                                \
        unsigned sa_ = (unsigned)__cvta_generic_to_shared(dst_ + idx_ * 4);       \
        asm volatile("cp.async.cg.shared.global [%0], [%1], 16;"                  \
                     :: "r"(sa_), "l"(src_ + idx_ * 4));                          \
    }                                                                             \
    asm volatile("cp.async.commit_group;" ::: "memory");                          \
} while (0)

// ---------------- persistent recurrence kernel ----------------
// 128 CTAs (one per SM, all co-resident), 256 threads.
// CTA g owns hidden units j = 4g..4g+3. smem: hs[512][64] (128KB) + Us[512][16] (32KB).
__global__ __launch_bounds__(256) void lstm_rec_k(const float* __restrict__ U,
                                                  float* __restrict__ out) {
    extern __shared__ float smem[];
    float* hs = smem;                 // staged h_{t-1}: [k][b]
    float* Us = smem + SS * BB;       // U slice: [k][l*4 + gate]

    const int tid  = threadIdx.x;
    const int w    = tid >> 5;
    const int lane = tid & 31;
    const int l    = w >> 1;                 // local hidden 0..3
    const int b    = ((w & 1) << 5) | lane;  // batch 0..63
    const int jb   = blockIdx.x * 4;
    const int j    = jb + l;

    // load the U slice once: Us[k][lh*4+gate] = U[k][gate*512 + jb + lh]
    for (int idx = tid; idx < HH * 16; idx += 256) {
        int k = idx >> 4, col = idx & 15;
        int gate = col & 3, lh = col >> 2;
        Us[idx] = U[(size_t)k * G4 + gate * HH + jb + lh];
    }

    float cst = 0.f;

    for (int t = 0; t < SS; ++t) {
        // prefetch x_proj terms (consumed only in the tail -> latency hidden)
        const float* xp = g_xpT + ((size_t)t * G4 + j) * BB + b;
        float x0 = xp[0];
        float x1 = xp[(size_t)HH * BB];
        float x2 = xp[(size_t)2 * HH * BB];
        float x3 = xp[(size_t)3 * HH * BB];
        float a0 = 0.f, a1 = 0.f, a2 = 0.f, a3 = 0.f;

        if (t > 0) {
            const float* rb = g_hbuf[(t + 1) & 1];   // h_{t-1}
            STAGE(0);
            STAGE(1);
            for (int ch = 0; ch < 8; ++ch) {
                if (ch < 7) asm volatile("cp.async.wait_group 1;" ::: "memory");
                else        asm volatile("cp.async.wait_group 0;" ::: "memory");
                __syncthreads();
                const float* hp = hs + ch * 64 * BB + b;
                const float* up = Us + ch * 64 * 16 + l * 4;
#pragma unroll 8
                for (int k = 0; k < 64; ++k) {
                    float  hv = hp[k * BB];
                    float4 u  = *(const float4*)(up + k * 16);
                    a0 += hv * u.x;
                    a1 += hv * u.y;
                    a2 += hv * u.z;
                    a3 += hv * u.w;
                }
                if (ch < 6) STAGE(ch + 2);
            }
        }

        // gates (split order: i, f, g, o)
        float i_ = sigf(a0 + x0);
        float f_ = sigf(a1 + x1);
        float g_ = tanhf_fast(a2 + x2);
        float o_ = sigf(a3 + x3);
        cst = f_ * cst + i_ * g_;
        float h = o_ * tanhf_fast(cst);

        out[((size_t)b * SS + t) * HH + j] = h;                 // hidden_seq [B,S,H]
        __stcg(&g_hbuf[t & 1][j * BB + b], h);                  // broadcast buffer (L2)
        if (t == SS - 1) {
            out[(size_t)BB * SS * HH + (size_t)b * HH + j] = h;             // h_f
            out[(size_t)BB * SS * HH + BB * HH + (size_t)b * HH + j] = cst; // c_f
        }

        // distributed global barrier (monotonic counter)
        __threadfence();
        __syncthreads();
        if (tid == 0) {
            atomicAdd(&g_ctr, 1u);
            unsigned tgt = (unsigned)NCTA * (unsigned)(t + 1);
            while (atomicAdd(&g_ctr, 0u) < tgt) { __nanosleep(32); }
        }
        __syncthreads();
    }
}

// ---------------- launch ----------------
extern "C" void kernel_launch(void* const* d_in, const int* in_sizes, int n_in,
                              void* d_out, int out_size) {
    const float* x = nullptr;
    const float* W = nullptr;
    const float* U = nullptr;
    const float* bias = nullptr;
    for (int i = 0; i < n_in; ++i) {
        int sz = in_sizes[i];
        if      (sz == BB * SS * II) x    = (const float*)d_in[i];
        else if (sz == II * G4)      W    = (const float*)d_in[i];
        else if (sz == HH * G4)      U    = (const float*)d_in[i];
        else if (sz == G4)           bias = (const float*)d_in[i];
    }
    float* out = (float*)d_out;
    if (!x || !W || !U || !bias) return;

    init_ctr_k<<<1, 1>>>();

    dim3 g1(16, 512);
    gemm1_k<<<g1, 256>>>(x, W, bias);

    size_t smem = (size_t)(SS * BB + HH * 16) * sizeof(float);   // 163840 B
    cudaFuncSetAttribute(lstm_rec_k, cudaFuncAttributeMaxDynamicSharedMemorySize, (int)smem);
    lstm_rec_k<<<NCTA, 256, smem>>>(U, out);
}

// round 9
// speedup vs baseline: 1.1022x; 1.1022x over previous
#include <cuda_runtime.h>
#include <cuda_bf16.h>

#define BB 64
#define SS 512
#define II 256
#define HH 512
#define G4 2048
#define NCTA 128   // 512 hidden / 4 per CTA

// ---------------- scratch (device globals: no allocation allowed) ----------------
__device__ float g_xpT[(size_t)SS * G4 * BB];   // x_proj transposed: [t][c][b], 256 MiB
__device__ float g_hbuf[2][HH * BB];            // ping-pong h broadcast: [j][b]
__device__ unsigned g_flag[NCTA];               // per-CTA completed-step counters

__global__ void init_flags_k() {
    if (threadIdx.x < NCTA) g_flag[threadIdx.x] = 0u;
}

// ---------------- GEMM1: xpT[t][c][b] = sum_i x[b][t][i]*W[i][c] + bias[c] ----------------
// grid = (16 c-tiles of 128, 512 t), block = 256. Tile: 128c x 64b, K=256 in BK=32 chunks.
__global__ __launch_bounds__(256) void gemm1_k(const float* __restrict__ x,
                                               const float* __restrict__ W,
                                               const float* __restrict__ bias) {
    __shared__ float Ws[32][132];
    __shared__ float xs[32][68];
    const int t  = blockIdx.y;
    const int c0 = blockIdx.x * 128;
    const int tid = threadIdx.x;
    const int tx = tid & 15;   // b group: 4 batches
    const int ty = tid >> 4;   // c group: 8 cols

    float acc[8][4];
#pragma unroll
    for (int i = 0; i < 8; ++i)
#pragma unroll
        for (int j = 0; j < 4; ++j) acc[i][j] = 0.f;

    for (int kk = 0; kk < II; kk += 32) {
#pragma unroll
        for (int i = 0; i < 16; ++i) {          // Ws: 32x128, coalesced along c
            int idx = i * 256 + tid;
            int k = idx >> 7, cl = idx & 127;
            Ws[k][cl] = W[(size_t)(kk + k) * G4 + c0 + cl];
        }
#pragma unroll
        for (int i = 0; i < 8; ++i) {           // xs: 32k x 64b, coalesced along k
            int idx = i * 256 + tid;
            int bl = idx >> 5, k = idx & 31;
            xs[k][bl] = x[((size_t)bl * SS + t) * II + kk + k];
        }
        __syncthreads();
#pragma unroll
        for (int k = 0; k < 32; ++k) {
            float4 xv = *(const float4*)&xs[k][tx * 4];
            float4 w0 = *(const float4*)&Ws[k][ty * 8];
            float4 w1 = *(const float4*)&Ws[k][ty * 8 + 4];
            float wv[8]  = {w0.x, w0.y, w0.z, w0.w, w1.x, w1.y, w1.z, w1.w};
            float xvv[4] = {xv.x, xv.y, xv.z, xv.w};
#pragma unroll
            for (int i = 0; i < 8; ++i)
#pragma unroll
                for (int j = 0; j < 4; ++j) acc[i][j] += wv[i] * xvv[j];
        }
        __syncthreads();
    }

#pragma unroll
    for (int i = 0; i < 8; ++i) {
        int c = c0 + ty * 8 + i;
        float bb = bias[c];
        float4 o = make_float4(acc[i][0] + bb, acc[i][1] + bb, acc[i][2] + bb, acc[i][3] + bb);
        *(float4*)&g_xpT[((size_t)t * G4 + c) * BB + tx * 4] = o;   // coalesced 256B rows
    }
}

// ---------------- recurrence helpers ----------------
__device__ __forceinline__ float sigf(float v) {
    v = fminf(fmaxf(v, -30.f), 30.f);
    return 1.f / (1.f + __expf(-v));
}
__device__ __forceinline__ float tanhf_fast(float v) {
    v = fminf(fmaxf(v, -15.f), 15.f);
    float e = __expf(-2.f * v);
    return (1.f - e) / (1.f + e);
}

__device__ __forceinline__ unsigned ld_flag_acq(const unsigned* p) {
    unsigned v;
    asm volatile("ld.global.acquire.gpu.u32 %0, [%1];" : "=r"(v) : "l"(p));
    return v;
}

#define STAGE(ch) do {                                                            \
    const float* src_ = rb + (ch) * 64 * BB;                                      \
    float* dst_ = hs + (ch) * 64 * BB;                                            \
    _Pragma("unroll")                                                             \
    for (int v_ = 0; v_ < 4; ++v_) {                                              \
        int idx_ = v_ * 256 + tid;                                                \
        unsigned sa_ = (unsigned)__cvta_generic_to_shared(dst_ + idx_ * 4);       \
        asm volatile("cp.async.cg.shared.global [%0], [%1], 16;"                  \
                     :: "r"(sa_), "l"(src_ + idx_ * 4));                          \
    }                                                                             \
    asm volatile("cp.async.commit_group;" ::: "memory");                          \
} while (0)

// blocking poll: wait until the 16 producer CTAs of chunk `ch` reach step `t`
#define POLL_BLOCK(ch) do {                                                       \
    unsigned fv_ = ld_flag_acq(&g_flag[(ch) * 16 + (tid & 15)]);                  \
    while (!__syncthreads_and(fv_ >= (unsigned)t)) {                              \
        __nanosleep(32);                                                          \
        fv_ = ld_flag_acq(&g_flag[(ch) * 16 + (tid & 15)]);                       \
    }                                                                             \
} while (0)

// ---------------- persistent recurrence kernel ----------------
// 128 CTAs (one per SM, all co-resident), 256 threads.
// CTA g owns hidden units j = 4g..4g+3. smem: hs[512][64] (128KB) + Us[512][16] (32KB).
__global__ __launch_bounds__(256) void lstm_rec_k(const float* __restrict__ U,
                                                  float* __restrict__ out) {
    extern __shared__ float smem[];
    float* hs = smem;                 // staged h_{t-1}: [k][b]
    float* Us = smem + SS * BB;       // U slice: [k][l*4 + gate]

    const int tid  = threadIdx.x;
    const int w    = tid >> 5;
    const int lane = tid & 31;
    const int l    = w >> 1;                 // local hidden 0..3
    const int b    = ((w & 1) << 5) | lane;  // batch 0..63
    const int jb   = blockIdx.x * 4;
    const int j    = jb + l;

    // load the U slice once: Us[k][lh*4+gate] = U[k][gate*512 + jb + lh]
    for (int idx = tid; idx < HH * 16; idx += 256) {
        int k = idx >> 4, col = idx & 15;
        int gate = col & 3, lh = col >> 2;
        Us[idx] = U[(size_t)k * G4 + gate * HH + jb + lh];
    }

    float cst = 0.f;

    for (int t = 0; t < SS; ++t) {
        // prefetch x_proj terms (consumed only in the tail -> latency hidden)
        const float* xp = g_xpT + ((size_t)t * G4 + j) * BB + b;
        float x0 = xp[0];
        float x1 = xp[(size_t)HH * BB];
        float x2 = xp[(size_t)2 * HH * BB];
        float x3 = xp[(size_t)3 * HH * BB];
        float a0 = 0.f, a1 = 0.f, a2 = 0.f, a3 = 0.f;

        if (t > 0) {
            const float* rb = g_hbuf[(t + 1) & 1];   // h_{t-1}
            POLL_BLOCK(0);
            STAGE(0);
            POLL_BLOCK(1);
            STAGE(1);
            for (int ch = 0; ch < 8; ++ch) {
                // issue flag loads for chunk ch+2 NOW; latency hides under compute(ch)
                unsigned fv = 0xffffffffu;
                if (ch < 6) fv = ld_flag_acq(&g_flag[(ch + 2) * 16 + (tid & 15)]);

                if (ch < 7) asm volatile("cp.async.wait_group 1;" ::: "memory");
                else        asm volatile("cp.async.wait_group 0;" ::: "memory");
                __syncthreads();

                const float* hp = hs + ch * 64 * BB + b;
                const float* up = Us + ch * 64 * 16 + l * 4;
#pragma unroll 8
                for (int k = 0; k < 64; ++k) {
                    float  hv = hp[k * BB];
                    float4 u  = *(const float4*)(up + k * 16);
                    a0 += hv * u.x;
                    a1 += hv * u.y;
                    a2 += hv * u.z;
                    a3 += hv * u.w;
                }

                if (ch < 6) {
                    // check prefetched flags; spin only if a producer lags
                    while (!__syncthreads_and(fv >= (unsigned)t)) {
                        __nanosleep(32);
                        fv = ld_flag_acq(&g_flag[(ch + 2) * 16 + (tid & 15)]);
                    }
                    STAGE(ch + 2);
                }
            }
        }

        // gates (split order: i, f, g, o)
        float i_ = sigf(a0 + x0);
        float f_ = sigf(a1 + x1);
        float g_ = tanhf_fast(a2 + x2);
        float o_ = sigf(a3 + x3);
        cst = f_ * cst + i_ * g_;
        float h = o_ * tanhf_fast(cst);

        out[((size_t)b * SS + t) * HH + j] = h;                 // hidden_seq [B,S,H]
        __stcg(&g_hbuf[t & 1][j * BB + b], h);                  // broadcast buffer (L2)
        if (t == SS - 1) {
            out[(size_t)BB * SS * HH + (size_t)b * HH + j] = h;             // h_f
            out[(size_t)BB * SS * HH + BB * HH + (size_t)b * HH + j] = cst; // c_f
        }

        // publish completion of step t: all threads' stores happen-before the
        // release store via __syncthreads() ordering (standard CUDA mem-model pattern)
        __syncthreads();
        if (tid == 0) {
            asm volatile("st.global.release.gpu.u32 [%0], %1;"
                         :: "l"(&g_flag[blockIdx.x]), "r"((unsigned)(t + 1)) : "memory");
        }
    }
}

// ---------------- launch ----------------
extern "C" void kernel_launch(void* const* d_in, const int* in_sizes, int n_in,
                              void* d_out, int out_size) {
    const float* x = nullptr;
    const float* W = nullptr;
    const float* U = nullptr;
    const float* bias = nullptr;
    for (int i = 0; i < n_in; ++i) {
        int sz = in_sizes[i];
        if      (sz == BB * SS * II) x    = (const float*)d_in[i];
        else if (sz == II * G4)      W    = (const float*)d_in[i];
        else if (sz == HH * G4)      U    = (const float*)d_in[i];
        else if (sz == G4)           bias = (const float*)d_in[i];
    }
    float* out = (float*)d_out;
    if (!x || !W || !U || !bias) return;

    init_flags_k<<<1, 128>>>();

    dim3 g1(16, 512);
    gemm1_k<<<g1, 256>>>(x, W, bias);

    size_t smem = (size_t)(SS * BB + HH * 16) * sizeof(float);   // 163840 B
    cudaFuncSetAttribute(lstm_rec_k, cudaFuncAttributeMaxDynamicSharedMemorySize, (int)smem);
    lstm_rec_k<<<NCTA, 256, smem>>>(U, out);
}

// round 14
// speedup vs baseline: 1.1962x; 1.0853x over previous
#include <cuda_runtime.h>
#include <cuda_bf16.h>

#define BB 64
#define SS 512
#define II 256
#define HH 512
#define G4 2048
#define NCTA 128   // 512 hidden / 4 per CTA

// ---------------- packed f32x2 helpers (sm_103a FFMA2 path) ----------------
#define FMA_X2(d, a, b, c) \
    asm("fma.rn.f32x2 %0, %1, %2, %3;" : "=l"(d) : "l"(a), "l"(b), "l"(c))
#define ADD_X2(d, a, b) \
    asm("add.rn.f32x2 %0, %1, %2;" : "=l"(d) : "l"(a), "l"(b))
#define SPLAT_X2(d, f) do { unsigned u_ = __float_as_uint(f); \
    asm("mov.b64 %0, {%1, %1};" : "=l"(d) : "r"(u_)); } while (0)
#define UNPK_X2(lo, hi, v) do { unsigned ulo_, uhi_; \
    asm("mov.b64 {%0, %1}, %2;" : "=r"(ulo_), "=r"(uhi_) : "l"(v)); \
    lo = __uint_as_float(ulo_); hi = __uint_as_float(uhi_); } while (0)

// ---------------- scratch (device globals: no allocation allowed) ----------------
__device__ float g_xpT[(size_t)SS * G4 * BB];   // x_proj transposed: [t][c][b], 256 MiB
__device__ float g_hbuf[2][HH * BB];            // ping-pong h broadcast: [j][b]
__device__ unsigned g_flag[NCTA];               // per-CTA completed-step counters

// ---------------- GEMM1 (FFMA2): xpT[t][c][b] = sum_i x[b][t][i]*W[i][c] + bias[c] ----
// grid = (16 c-tiles of 128, 512 t), block = 256. Tile: 128c x 64b, K=256 in BK=32 chunks.
__global__ __launch_bounds__(256) void gemm1_k(const float* __restrict__ x,
                                               const float* __restrict__ W,
                                               const float* __restrict__ bias) {
    __shared__ float Ws[32][132];
    __shared__ float xs[32][68];
    const int t  = blockIdx.y;
    const int c0 = blockIdx.x * 128;
    const int tid = threadIdx.x;
    const int tx = tid & 15;   // b group: 4 batches
    const int ty = tid >> 4;   // c group: 8 cols

    // fold flag reset into this kernel (kernel boundary orders it before rec)
    if (blockIdx.x == 0 && blockIdx.y == 0 && tid < NCTA) g_flag[tid] = 0u;

    unsigned long long accp[16];   // [i 0..7][pair 0..1]
#pragma unroll
    for (int i = 0; i < 16; ++i) accp[i] = 0ULL;

    for (int kk = 0; kk < II; kk += 32) {
#pragma unroll
        for (int i = 0; i < 16; ++i) {          // Ws: 32x128, coalesced along c
            int idx = i * 256 + tid;
            int k = idx >> 7, cl = idx & 127;
            Ws[k][cl] = W[(size_t)(kk + k) * G4 + c0 + cl];
        }
#pragma unroll
        for (int i = 0; i < 8; ++i) {           // xs: 32k x 64b, coalesced along k
            int idx = i * 256 + tid;
            int bl = idx >> 5, k = idx & 31;
            xs[k][bl] = x[((size_t)bl * SS + t) * II + kk + k];
        }
        __syncthreads();
#pragma unroll
        for (int k = 0; k < 32; ++k) {
            ulonglong2 xp2 = *(const ulonglong2*)&xs[k][tx * 4];   // {b0,b1},{b2,b3}
            float4 w0 = *(const float4*)&Ws[k][ty * 8];
            float4 w1 = *(const float4*)&Ws[k][ty * 8 + 4];
            unsigned long long ws[8];
            SPLAT_X2(ws[0], w0.x); SPLAT_X2(ws[1], w0.y);
            SPLAT_X2(ws[2], w0.z); SPLAT_X2(ws[3], w0.w);
            SPLAT_X2(ws[4], w1.x); SPLAT_X2(ws[5], w1.y);
            SPLAT_X2(ws[6], w1.z); SPLAT_X2(ws[7], w1.w);
#pragma unroll
            for (int i = 0; i < 8; ++i) {
                FMA_X2(accp[i * 2 + 0], ws[i], xp2.x, accp[i * 2 + 0]);
                FMA_X2(accp[i * 2 + 1], ws[i], xp2.y, accp[i * 2 + 1]);
            }
        }
        __syncthreads();
    }

#pragma unroll
    for (int i = 0; i < 8; ++i) {
        int c = c0 + ty * 8 + i;
        float bb = bias[c];
        float a0, a1, a2, a3;
        UNPK_X2(a0, a1, accp[i * 2 + 0]);
        UNPK_X2(a2, a3, accp[i * 2 + 1]);
        float4 o = make_float4(a0 + bb, a1 + bb, a2 + bb, a3 + bb);
        *(float4*)&g_xpT[((size_t)t * G4 + c) * BB + tx * 4] = o;   // coalesced 256B rows
    }
}

// ---------------- recurrence helpers ----------------
__device__ __forceinline__ float sigf(float v) {
    v = fminf(fmaxf(v, -30.f), 30.f);
    return 1.f / (1.f + __expf(-v));
}
__device__ __forceinline__ float tanhf_fast(float v) {
    v = fminf(fmaxf(v, -15.f), 15.f);
    float e = __expf(-2.f * v);
    return (1.f - e) / (1.f + e);
}
__device__ __forceinline__ unsigned ld_flag_acq(const unsigned* p) {
    unsigned v;
    asm volatile("ld.global.acquire.gpu.u32 %0, [%1];" : "=r"(v) : "l"(p));
    return v;
}

// stage one 32KB chunk (128 k-rows x 64 b) of h from L2 into smem
#define STAGE(ch) do {                                                            \
    const float* src_ = rb + (ch) * 128 * BB;                                     \
    float* dst_ = hs + (ch) * 128 * BB;                                           \
    _Pragma("unroll")                                                             \
    for (int v_ = 0; v_ < 8; ++v_) {                                              \
        int idx_ = v_ * 256 + tid;                                                \
        unsigned sa_ = (unsigned)__cvta_generic_to_shared(dst_ + idx_ * 4);       \
        asm volatile("cp.async.cg.shared.global [%0], [%1], 16;"                  \
                     :: "r"(sa_), "l"(src_ + idx_ * 4));                          \
    }                                                                             \
    asm volatile("cp.async.commit_group;" ::: "memory");                          \
} while (0)

// blocking poll: wait until the 32 producer CTAs of chunk `ch` reach step `t`
#define POLL_BLOCK(ch) do {                                                       \
    unsigned fv_ = ld_flag_acq(&g_flag[(ch) * 32 + (tid & 31)]);                  \
    while (!__syncthreads_and(fv_ >= (unsigned)t)) {                              \
        __nanosleep(32);                                                          \
        fv_ = ld_flag_acq(&g_flag[(ch) * 32 + (tid & 31)]);                       \
    }                                                                             \
} while (0)

// ---------------- persistent recurrence kernel ----------------
// 128 CTAs (one per SM, co-resident), 256 threads.
// thread = (l = unit 0..3, bq = b-quad 0..15, kq = k-quarter 0..3)
// 16 accumulators per thread as 8 f32x2; k-quarter partials reduced via smem.
// smem: hs[512][64] (128KB) + Us[512][16] (32KB).
__global__ __launch_bounds__(256) void lstm_rec_k(const float* __restrict__ U,
                                                  float* __restrict__ out) {
    extern __shared__ float smem[];
    float* hs = smem;                 // staged h_{t-1}: [k][b]
    float* Us = smem + SS * BB;       // U slice: [k][l*4 + gate]

    const int tid = threadIdx.x;
    const int bq  = tid & 15;          // b quad -> b = 4*bq .. 4*bq+3
    const int l   = (tid >> 4) & 3;    // local hidden unit
    const int kq  = tid >> 6;          // k quarter within chunk
    const int b4  = bq * 4;
    const int jb  = blockIdx.x * 4;
    const int j   = jb + l;

    // load the U slice once: Us[k][lh*4+gate] = U[k][gate*512 + jb + lh]
    for (int idx = tid; idx < HH * 16; idx += 256) {
        int k = idx >> 4, col = idx & 15;
        int gate = col & 3, lh = col >> 2;
        Us[idx] = U[(size_t)k * G4 + gate * HH + jb + lh];
    }

    float c0s = 0.f, c1s = 0.f, c2s = 0.f, c3s = 0.f;   // cell state (kq==0 threads)

    for (int t = 0; t < SS; ++t) {
        // prefetch x_proj terms (only the gate-computing threads need them)
        float4 xp0, xp1, xp2g, xp3;
        if (kq == 0) {
            const float* xp = g_xpT + ((size_t)t * G4 + j) * BB + b4;
            xp0  = *(const float4*)(xp);
            xp1  = *(const float4*)(xp + (size_t)HH * BB);
            xp2g = *(const float4*)(xp + (size_t)2 * HH * BB);
            xp3  = *(const float4*)(xp + (size_t)3 * HH * BB);
        }

        unsigned long long acc[8];   // [gate g][b-pair p] = acc[g*2+p]
#pragma unroll
        for (int i = 0; i < 8; ++i) acc[i] = 0ULL;

        if (t > 0) {
            const float* rb = g_hbuf[(t + 1) & 1];   // h_{t-1}
            POLL_BLOCK(0);
            STAGE(0);
            POLL_BLOCK(1);
            STAGE(1);
            for (int ch = 0; ch < 4; ++ch) {
                // flag loads for chunk ch+2 fly under compute(ch)
                unsigned fv = 0xffffffffu;
                if (ch < 2) fv = ld_flag_acq(&g_flag[(ch + 2) * 32 + (tid & 31)]);

                if (ch < 3) asm volatile("cp.async.wait_group 1;" ::: "memory");
                else        asm volatile("cp.async.wait_group 0;" ::: "memory");
                __syncthreads();

                const int kbase = ch * 128 + kq * 32;
                unsigned hA = (unsigned)__cvta_generic_to_shared(hs + (size_t)kbase * BB + b4);
                const float* up = Us + (size_t)kbase * 16 + l * 4;
#pragma unroll
                for (int k = 0; k < 32; ++k) {
                    unsigned long long h01, h23;
                    asm volatile("ld.shared.v2.b64 {%0, %1}, [%2];"
                                 : "=l"(h01), "=l"(h23) : "r"(hA + k * (BB * 4)));
                    float4 u = *(const float4*)(up + k * 16);
                    unsigned long long u0, u1, u2, u3;
                    SPLAT_X2(u0, u.x); SPLAT_X2(u1, u.y);
                    SPLAT_X2(u2, u.z); SPLAT_X2(u3, u.w);
                    FMA_X2(acc[0], u0, h01, acc[0]);
                    FMA_X2(acc[1], u0, h23, acc[1]);
                    FMA_X2(acc[2], u1, h01, acc[2]);
                    FMA_X2(acc[3], u1, h23, acc[3]);
                    FMA_X2(acc[4], u2, h01, acc[4]);
                    FMA_X2(acc[5], u2, h23, acc[5]);
                    FMA_X2(acc[6], u3, h01, acc[6]);
                    FMA_X2(acc[7], u3, h23, acc[7]);
                }

                if (ch < 2) {
                    while (!__syncthreads_and(fv >= (unsigned)t)) {
                        __nanosleep(32);
                        fv = ld_flag_acq(&g_flag[(ch + 2) * 32 + (tid & 31)]);
                    }
                    STAGE(ch + 2);
                }
            }
        }

        // ---- reduce k-quarter partials (kq 1..3 -> smem scratch; kq 0 sums) ----
        if (kq != 0) {
            ulonglong2* dst = (ulonglong2*)(hs + (((kq - 1) * 64 + (tid & 63)) << 4));
            dst[0] = make_ulonglong2(acc[0], acc[1]);
            dst[1] = make_ulonglong2(acc[2], acc[3]);
            dst[2] = make_ulonglong2(acc[4], acc[5]);
            dst[3] = make_ulonglong2(acc[6], acc[7]);
        }
        __syncthreads();

        if (kq == 0) {
#pragma unroll
            for (int q = 0; q < 3; ++q) {
                const ulonglong2* src = (const ulonglong2*)(hs + ((q * 64 + tid) << 4));
#pragma unroll
                for (int r = 0; r < 4; ++r) {
                    ulonglong2 v = src[r];
                    ADD_X2(acc[2 * r + 0], acc[2 * r + 0], v.x);
                    ADD_X2(acc[2 * r + 1], acc[2 * r + 1], v.y);
                }
            }
            float a[4][4];   // [gate][b]
#pragma unroll
            for (int g = 0; g < 4; ++g) {
                UNPK_X2(a[g][0], a[g][1], acc[g * 2 + 0]);
                UNPK_X2(a[g][2], a[g][3], acc[g * 2 + 1]);
            }
            float xg0[4] = {xp0.x, xp0.y, xp0.z, xp0.w};
            float xg1[4] = {xp1.x, xp1.y, xp1.z, xp1.w};
            float xg2[4] = {xp2g.x, xp2g.y, xp2g.z, xp2g.w};
            float xg3[4] = {xp3.x, xp3.y, xp3.z, xp3.w};
            float cst[4] = {c0s, c1s, c2s, c3s};
            float hv[4];
#pragma unroll
            for (int i = 0; i < 4; ++i) {
                float i_ = sigf(a[0][i] + xg0[i]);
                float f_ = sigf(a[1][i] + xg1[i]);
                float g_ = tanhf_fast(a[2][i] + xg2[i]);
                float o_ = sigf(a[3][i] + xg3[i]);
                cst[i] = f_ * cst[i] + i_ * g_;
                hv[i]  = o_ * tanhf_fast(cst[i]);
            }
            c0s = cst[0]; c1s = cst[1]; c2s = cst[2]; c3s = cst[3];

            // outputs
#pragma unroll
            for (int i = 0; i < 4; ++i)
                out[((size_t)(b4 + i) * SS + t) * HH + j] = hv[i];
            __stcg((float4*)&g_hbuf[t & 1][j * BB + b4],
                   make_float4(hv[0], hv[1], hv[2], hv[3]));
            if (t == SS - 1) {
#pragma unroll
                for (int i = 0; i < 4; ++i) {
                    out[(size_t)BB * SS * HH + (size_t)(b4 + i) * HH + j] = hv[i];
                    out[(size_t)BB * SS * HH + BB * HH + (size_t)(b4 + i) * HH + j] = cst[i];
                }
            }
        }

        // publish completion of step t (all stores ordered before release via bar)
        __syncthreads();
        if (tid == 0) {
            asm volatile("st.global.release.gpu.u32 [%0], %1;"
                         :: "l"(&g_flag[blockIdx.x]), "r"((unsigned)(t + 1)) : "memory");
        }
    }
}

// ---------------- launch ----------------
extern "C" void kernel_launch(void* const* d_in, const int* in_sizes, int n_in,
                              void* d_out, int out_size) {
    const float* x = nullptr;
    const float* W = nullptr;
    const float* U = nullptr;
    const float* bias = nullptr;
    for (int i = 0; i < n_in; ++i) {
        int sz = in_sizes[i];
        if      (sz == BB * SS * II) x    = (const float*)d_in[i];
        else if (sz == II * G4)      W    = (const float*)d_in[i];
        else if (sz == HH * G4)      U    = (const float*)d_in[i];
        else if (sz == G4)           bias = (const float*)d_in[i];
    }
    float* out = (float*)d_out;
    if (!x || !W || !U || !bias) return;

    dim3 g1(16, 512);
    gemm1_k<<<g1, 256>>>(x, W, bias);

    size_t smem = (size_t)(SS * BB + HH * 16) * sizeof(float);   // 163840 B
    cudaFuncSetAttribute(lstm_rec_k, cudaFuncAttributeMaxDynamicSharedMemorySize, (int)smem);
    lstm_rec_k<<<NCTA, 256, smem>>>(U, out);
}